// round 5
// baseline (speedup 1.0000x reference)
#include <cuda_runtime.h>
#include <math.h>
#include <stdint.h>

#define BATCH 4
#define CIN   512
#define HID   64
#define NCLS  11
#define H1    60
#define W1    80
#define P1    4800
#define H2    30
#define W2    40
#define P2    1200
#define HO    480
#define WO    640
#define PO    307200
#define THRESH 500

#define PROB_ELEMS ((size_t)BATCH*NCLS*PO)
#define SEG_ELEMS  ((size_t)BATCH*PO)

#define TILES1 38            // ceil(4800/128)
#define TILES2 10            // ceil(1200/128)
#define RS_BX  5             // 640/128
#define RS_BY  60            // 480/8
#define RS_BLOCKS (RS_BX*RS_BY*BATCH)   // 1200

// -------- scratch (no allocations allowed) --------
__device__ float g_f1s[2][BATCH*HID*P1];   // K-split halves, no bias/relu
__device__ float g_f2s[2][BATCH*HID*P2];
__device__ float g_ls[BATCH*NCLS*P1];
__device__ int g_cnt[36], g_minx[36], g_maxx[36], g_miny[36], g_maxy[36];
__device__ unsigned g_done;

// packed fp32x2 FMA (sm_100+): 2 fp32 FMAs per issue slot
__device__ __forceinline__ float2 ffma2(float2 a, float2 b, float2 c) {
    float2 d;
    asm("fma.rn.f32x2 %0, %1, %2, %3;"
        : "=l"(*(unsigned long long*)&d)
        : "l"(*(unsigned long long*)&a),
          "l"(*(unsigned long long*)&b),
          "l"(*(unsigned long long*)&c));
    return d;
}

__device__ __forceinline__ void cp16(uint32_t s, const float* g) {
    asm volatile("cp.async.cg.shared.global [%0], [%1], 16;" :: "r"(s), "l"(g));
}
__device__ __forceinline__ void cp_commit() {
    asm volatile("cp.async.commit_group;");
}
__device__ __forceinline__ void cp_wait0() {
    asm volatile("cp.async.wait_group 0;");
}

// ============================================================
// Stage 1: 1x1 conv GEMM, K-split 2, double-buffered via cp.async.
// Tile: 128 px x 64 oc x 256 channels. 256 threads.
// Thread: 8 px (4 f32x2) x 4 oc = 16 float2 acc.
// ============================================================
__global__ void __launch_bounds__(256)
conv_kernel(const float* __restrict__ f1in, const float* __restrict__ f2in,
            const float* __restrict__ w1, const float* __restrict__ w2)
{
    __shared__ alignas(16) float  As[2][32][128];
    __shared__ alignas(16) float2 Bs[2][32][66];

    const int tid = threadIdx.x;
    const int bx = blockIdx.x, kh = blockIdx.y, b = blockIdx.z;

    // bbox/ticket init (runs 2 kernels before resize consumes it)
    if (bx == 0 && kh == 0 && b == 0 && tid < 64) {
        if (tid < 36) {
            g_cnt[tid] = 0;
            g_minx[tid] = 0x7fffffff; g_maxx[tid] = -1;
            g_miny[tid] = 0x7fffffff; g_maxy[tid] = -1;
        }
        if (tid == 63) g_done = 0;
    }

    const float* in; const float* w; float* out; int P, p0;
    if (bx < TILES1) { in = f1in; w = w1; out = g_f1s[kh]; P = P1; p0 = bx * 128; }
    else             { in = f2in; w = w2; out = g_f2s[kh]; P = P2; p0 = (bx - TILES1) * 128; }
    const float* inb = in + (size_t)b * CIN * P;
    const int k0base = kh * 256;

    const int tp = tid & 15;
    const int to = tid >> 4;

    const uint32_t as_base = (uint32_t)__cvta_generic_to_shared(&As[0][0][0]);

    float2 acc[4][4];
#pragma unroll
    for (int i = 0; i < 4; i++)
#pragma unroll
        for (int j = 0; j < 4; j++) acc[i][j] = make_float2(0.f, 0.f);

    float br[8];

    // ---- prologue: stage k-block 0 ----
    {
        const int k0 = k0base;
#pragma unroll
        for (int q = 0; q < 4; q++) {
            int l = tid + q * 256;
            int row = l >> 5, c4 = l & 31;
            int px = p0 + c4 * 4; if (px > P - 4) px = P - 4;
            cp16(as_base + (uint32_t)(row * 128 + c4 * 4) * 4,
                 inb + (size_t)(k0 + row) * P + px);
        }
        cp_commit();
#pragma unroll
        for (int q = 0; q < 8; q++) {
            int l = tid + q * 256;
            int o = l >> 5, kk = l & 31;
            br[q] = w[o * CIN + k0 + kk];
        }
#pragma unroll
        for (int q = 0; q < 8; q++) {
            int l = tid + q * 256;
            int o = l >> 5, kk = l & 31;
            Bs[0][kk][o] = make_float2(br[q], br[q]);
        }
        cp_wait0();
        __syncthreads();
    }

#pragma unroll 1
    for (int kb = 0; kb < 8; kb++) {
        const int cb = kb & 1;
        const int nb = cb ^ 1;
        if (kb < 7) {
            const int k0 = k0base + (kb + 1) * 32;
#pragma unroll
            for (int q = 0; q < 4; q++) {
                int l = tid + q * 256;
                int row = l >> 5, c4 = l & 31;
                int px = p0 + c4 * 4; if (px > P - 4) px = P - 4;
                cp16(as_base + (uint32_t)(nb * 32 * 128 + row * 128 + c4 * 4) * 4,
                     inb + (size_t)(k0 + row) * P + px);
            }
            cp_commit();
#pragma unroll
            for (int q = 0; q < 8; q++) {
                int l = tid + q * 256;
                int o = l >> 5, kk = l & 31;
                br[q] = w[o * CIN + k0 + kk];
            }
        }
        // ---- compute on buffer cb ----
#pragma unroll
        for (int kk = 0; kk < 32; kk++) {
            float4 a0 = *(const float4*)&As[cb][kk][tp * 4];
            float4 a1 = *(const float4*)&As[cb][kk][64 + tp * 4];
            float4 bq0 = *(const float4*)&Bs[cb][kk][to * 4];
            float4 bq1 = *(const float4*)&Bs[cb][kk][to * 4 + 2];
            float2 ap[4] = { {a0.x,a0.y},{a0.z,a0.w},{a1.x,a1.y},{a1.z,a1.w} };
            float2 bv[4] = { {bq0.x,bq0.y},{bq0.z,bq0.w},{bq1.x,bq1.y},{bq1.z,bq1.w} };
#pragma unroll
            for (int i = 0; i < 4; i++)
#pragma unroll
                for (int j = 0; j < 4; j++)
                    acc[i][j] = ffma2(ap[i], bv[j], acc[i][j]);
        }
        __syncthreads();
        if (kb < 7) {
#pragma unroll
            for (int q = 0; q < 8; q++) {
                int l = tid + q * 256;
                int o = l >> 5, kk = l & 31;
                Bs[nb][kk][o] = make_float2(br[q], br[q]);
            }
            cp_wait0();
            __syncthreads();
        }
    }

    // ---- store partial sums (no bias/relu; fuse stage applies them) ----
    float* outb = out + (size_t)b * HID * P;
#pragma unroll
    for (int j = 0; j < 4; j++) {
        int oc = to * 4 + j;
        float* op = outb + (size_t)oc * P;
#pragma unroll
        for (int i = 0; i < 4; i++) {
            int px = p0 + ((i < 2) ? (tp * 4 + i * 2) : (64 + tp * 4 + (i - 2) * 2));
            if (px < P) *(float2*)&op[px] = acc[i][j];
        }
    }
}

// ============================================================
// Stage 2: logits_small = wc * (relu(f1)+up2(relu(f2))) + bc at 60x80.
// 2 threads per pixel (h-split), shfl-pair reduce.
// ============================================================
__global__ void __launch_bounds__(256)
fuse_kernel(const float* __restrict__ wc, const float* __restrict__ bc,
            const float* __restrict__ b1, const float* __restrict__ b2)
{
    __shared__ float s_wc[NCLS * HID];
    __shared__ float s_b1[HID], s_b2[HID], s_bc[NCLS];
    const int tid = threadIdx.x;
    for (int i = tid; i < NCLS * HID; i += 256) s_wc[i] = wc[i];
    if (tid < HID) { s_b1[tid] = b1[tid]; s_b2[tid] = b2[tid]; }
    if (tid < NCLS) s_bc[tid] = bc[tid];
    __syncthreads();

    const int pl = tid >> 1;
    const int hh = (tid & 1) * 32;
    const int p = blockIdx.x * 128 + pl;
    const int b = blockIdx.y;
    const bool valid = (p < P1);
    const int pp = valid ? p : P1 - 1;
    const int y = pp / W1, x = pp % W1;

    // half-pixel bilinear into 30x40 with edge clamp
    float fx = 0.5f * x - 0.25f;
    int ix0 = (int)floorf(fx); float tx = fx - (float)ix0;
    int ix0c = max(ix0, 0), ix1c = min(ix0 + 1, W2 - 1);
    float fy = 0.5f * y - 0.25f;
    int iy0 = (int)floorf(fy); float ty = fy - (float)iy0;
    int iy0c = max(iy0, 0), iy1c = min(iy0 + 1, H2 - 1);
    int i00 = iy0c * W2 + ix0c, i01 = iy0c * W2 + ix1c;
    int i10 = iy1c * W2 + ix0c, i11 = iy1c * W2 + ix1c;

    const float* f1a = g_f1s[0] + (size_t)b * HID * P1 + pp;
    const float* f1b = g_f1s[1] + (size_t)b * HID * P1 + pp;
    const float* f2a = g_f2s[0] + (size_t)b * HID * P2;
    const float* f2b = g_f2s[1] + (size_t)b * HID * P2;

    float acc[NCLS];
#pragma unroll
    for (int c = 0; c < NCLS; c++) acc[c] = 0.f;

#pragma unroll 4
    for (int h = hh; h < hh + 32; h++) {
        float s = fmaxf(f1a[(size_t)h * P1] + f1b[(size_t)h * P1] + s_b1[h], 0.f);
        const float* ca = f2a + (size_t)h * P2;
        const float* cb2 = f2b + (size_t)h * P2;
        float bb = s_b2[h];
        float v00 = fmaxf(ca[i00] + cb2[i00] + bb, 0.f);
        float v01 = fmaxf(ca[i01] + cb2[i01] + bb, 0.f);
        float v10 = fmaxf(ca[i10] + cb2[i10] + bb, 0.f);
        float v11 = fmaxf(ca[i11] + cb2[i11] + bb, 0.f);
        float v0 = v00 + tx * (v01 - v00);
        float v1 = v10 + tx * (v11 - v10);
        s += v0 + ty * (v1 - v0);
#pragma unroll
        for (int c = 0; c < NCLS; c++) acc[c] = fmaf(s_wc[c * HID + h], s, acc[c]);
    }

#pragma unroll
    for (int c = 0; c < NCLS; c++)
        acc[c] += __shfl_xor_sync(0xffffffffu, acc[c], 1);

    if ((tid & 1) == 0 && valid) {
        float* lsb = g_ls + (size_t)b * NCLS * P1 + p;
#pragma unroll
        for (int c = 0; c < NCLS; c++) lsb[(size_t)c * P1] = acc[c] + s_bc[c];
    }
}

// ============================================================
// Stage 3: resize8 -> softmax -> prob + seg + bbox; last block finalizes.
// Block: 32x8 threads, 4 px/thread -> 128x8 output tile.
// ============================================================
__global__ void __launch_bounds__(256)
resize_kernel(float* __restrict__ out)
{
    __shared__ float st[NCLS][3][18];
    __shared__ int s_cnt[9], s_minx[9], s_maxx[9], s_miny[9], s_maxy[9];
    __shared__ unsigned s_ticket;

    const int tx0 = threadIdx.x, ty0 = threadIdx.y;
    const int tid = ty0 * 32 + tx0;
    if (tid < 9) {
        s_cnt[tid] = 0;
        s_minx[tid] = 0x7fffffff; s_maxx[tid] = -1;
        s_miny[tid] = 0x7fffffff; s_maxy[tid] = -1;
    }

    const int bx = blockIdx.x, by = blockIdx.y, b = blockIdx.z;
    const float* ls = g_ls + (size_t)b * NCLS * P1;

    for (int i = tid; i < NCLS * 3 * 18; i += 256) {
        int c = i / 54; int rk = i % 54; int r = rk / 18; int k = rk % 18;
        int col = min(max(bx * 16 - 1 + k, 0), W1 - 1);
        int row = min(max(by - 1 + r, 0), H1 - 1);
        st[c][r][k] = ls[(size_t)c * P1 + row * W1 + col];
    }
    __syncthreads();

    const int Xb = bx * 128 + tx0 * 4;
    const int Y  = by * 8 + ty0;
    const int odd = tx0 & 1;
    const int c0 = (tx0 >> 1) + odd;            // shared source column pair (c0, c0+1)
    const int r0 = (ty0 < 4) ? 0 : 1;
    const float ty = (ty0 < 4) ? (float)(2 * ty0 + 9) * (1.f / 16.f)
                               : (float)(2 * ty0 - 7) * (1.f / 16.f);
    float txw[4];
#pragma unroll
    for (int j = 0; j < 4; j++) {
        int jx = odd * 4 + j;
        txw[j] = (jx < 4) ? (float)(2 * jx + 9) * (1.f / 16.f)
                          : (float)(2 * jx - 7) * (1.f / 16.f);
    }

    float Av[NCLS], Dv[NCLS];
#pragma unroll
    for (int c = 0; c < NCLS; c++) {
        float a0 = st[c][r0][c0],     b0v = st[c][r0][c0 + 1];
        float a1 = st[c][r0 + 1][c0], b1v = st[c][r0 + 1][c0 + 1];
        float A = a0 + ty * (a1 - a0);
        float B = b0v + ty * (b1v - b0v);
        Av[c] = A; Dv[c] = B - A;
    }

    float e[4][NCLS];
    int arg[4];
    float inv[4];
#pragma unroll
    for (int j = 0; j < 4; j++) {
        float mm = -1e30f; int aa = 0;
#pragma unroll
        for (int c = 0; c < NCLS; c++) {
            float v = fmaf(txw[j], Dv[c], Av[c]);
            e[j][c] = v;
            if (v > mm) { mm = v; aa = c; }
        }
        arg[j] = aa;
        float s = 0.f;
#pragma unroll
        for (int c = 0; c < NCLS; c++) {
            float ex = __expf(e[j][c] - mm);
            e[j][c] = ex; s += ex;
        }
        inv[j] = 1.f / s;
    }

    const size_t base = (size_t)b * NCLS * PO + (size_t)Y * WO + Xb;
#pragma unroll
    for (int c = 0; c < NCLS; c++) {
        float4 v4 = make_float4(e[0][c] * inv[0], e[1][c] * inv[1],
                                e[2][c] * inv[2], e[3][c] * inv[3]);
        *(float4*)&out[base + (size_t)c * PO] = v4;
    }
    *(float4*)&out[PROB_ELEMS + (size_t)b * PO + (size_t)Y * WO + Xb] =
        make_float4((float)arg[0], (float)arg[1], (float)arg[2], (float)arg[3]);

    // bbox smem reduce (dedup classes within the 4-px strip; Y constant)
#pragma unroll
    for (int j = 0; j < 4; j++) {
        int c = arg[j];
        if (c < 1 || c > 9) continue;
        bool dup = false;
#pragma unroll
        for (int jj = 0; jj < 4; jj++) if (jj < j && arg[jj] == c) dup = true;
        if (dup) continue;
        int cnt = 1, mx = Xb + j;
#pragma unroll
        for (int jj = 0; jj < 4; jj++) if (jj > j && arg[jj] == c) { cnt++; mx = Xb + jj; }
        int k = c - 1;
        atomicAdd(&s_cnt[k], cnt);
        atomicMin(&s_minx[k], Xb + j); atomicMax(&s_maxx[k], mx);
        atomicMin(&s_miny[k], Y);      atomicMax(&s_maxy[k], Y);
    }
    __syncthreads();
    if (tid < 9 && s_cnt[tid] > 0) {
        int g = b * 9 + tid;
        atomicAdd(&g_cnt[g], s_cnt[tid]);
        atomicMin(&g_minx[g], s_minx[tid]); atomicMax(&g_maxx[g], s_maxx[tid]);
        atomicMin(&g_miny[g], s_miny[tid]); atomicMax(&g_maxy[g], s_maxy[tid]);
    }

    // last-finishing block finalizes bbx rows
    __threadfence();
    __syncthreads();
    if (tid == 0) s_ticket = atomicAdd(&g_done, 1u);
    __syncthreads();
    if (s_ticket == RS_BLOCKS - 1 && tid < 36) {
        __threadfence();
        int cnt = atomicAdd(&g_cnt[tid], 0);
        float* row = out + PROB_ELEMS + SEG_ELEMS + (size_t)tid * 6;
        if (cnt >= THRESH) {
            row[0] = (float)(tid / 9);
            row[1] = (float)atomicAdd(&g_minx[tid], 0);
            row[2] = (float)atomicAdd(&g_miny[tid], 0);
            row[3] = (float)atomicAdd(&g_maxx[tid], 0);
            row[4] = (float)atomicAdd(&g_maxy[tid], 0);
            row[5] = (float)(tid % 9 + 1);
        } else {
            row[0] = -1.f; row[1] = -1.f; row[2] = -1.f;
            row[3] = -1.f; row[4] = -1.f; row[5] = -1.f;
        }
    }
}

// ============================================================
extern "C" void kernel_launch(void* const* d_in, const int* in_sizes, int n_in,
                              void* d_out, int out_size)
{
    const float* feature1 = (const float*)d_in[0];
    const float* feature2 = (const float*)d_in[1];
    const float* w1 = (const float*)d_in[2];
    const float* b1 = (const float*)d_in[3];
    const float* w2 = (const float*)d_in[4];
    const float* b2 = (const float*)d_in[5];
    const float* wc = (const float*)d_in[6];
    const float* bc = (const float*)d_in[7];
    float* out = (float*)d_out;

    conv_kernel<<<dim3(TILES1 + TILES2, 2, BATCH), 256>>>(feature1, feature2, w1, w2);
    fuse_kernel<<<dim3(38, BATCH), 256>>>(wc, bc, b1, b2);
    resize_kernel<<<dim3(RS_BX, RS_BY, BATCH), dim3(32, 8)>>>(out);
}

// round 6
// speedup vs baseline: 1.4842x; 1.4842x over previous
#include <cuda_runtime.h>
#include <math.h>
#include <stdint.h>

#define BATCH 4
#define CIN   512
#define HID   64
#define NCLS  11
#define H1    60
#define W1    80
#define P1    4800
#define H2    30
#define W2    40
#define P2    1200
#define HO    480
#define WO    640
#define PO    307200
#define THRESH 500

#define PROB_ELEMS ((size_t)BATCH*NCLS*PO)
#define SEG_ELEMS  ((size_t)BATCH*PO)

#define TILES1 38            // ceil(4800/128)
#define TILES2 10            // ceil(1200/128)
#define RS_BX  5
#define RS_BY  60
#define RS_BLOCKS (RS_BX*RS_BY*BATCH)   // 1200

// -------- scratch --------
__device__ float g_f1s[2][BATCH*HID*P1];
__device__ float g_f2s[2][BATCH*HID*P2];
__device__ float g_ls[BATCH*NCLS*P1];
__device__ int g_cnt[36], g_minx[36], g_maxx[36], g_miny[36], g_maxy[36];
__device__ unsigned g_done;

__device__ __forceinline__ float2 ffma2(float2 a, float2 b, float2 c) {
    float2 d;
    asm("fma.rn.f32x2 %0, %1, %2, %3;"
        : "=l"(*(unsigned long long*)&d)
        : "l"(*(unsigned long long*)&a),
          "l"(*(unsigned long long*)&b),
          "l"(*(unsigned long long*)&c));
    return d;
}

__device__ __forceinline__ void cp16(uint32_t s, const float* g) {
    asm volatile("cp.async.cg.shared.global [%0], [%1], 16;" :: "r"(s), "l"(g));
}
__device__ __forceinline__ void cp_commit() {
    asm volatile("cp.async.commit_group;");
}
__device__ __forceinline__ void cp_wait0() {
    asm volatile("cp.async.wait_group 0;");
}

// ============================================================
// Stage 1: 1x1 conv GEMM, K-split 2, cp.async double-buffered.
// Tile: 128 px x 64 oc x 256 ch. 256 threads.
// Thread: 4 px (lane*4) x 8 oc (warp-uniform group) = 16 float2 acc.
// A: 1 LDS.128/kk; B: 4 broadcast LDS.128/kk -> crossbar == fma floor.
// ============================================================
__global__ void __launch_bounds__(256)
conv_kernel(const float* __restrict__ f1in, const float* __restrict__ f2in,
            const float* __restrict__ w1, const float* __restrict__ w2)
{
    __shared__ alignas(16) float  As[2][32][128];
    __shared__ alignas(16) float2 Bs[2][32][66];

    const int tid = threadIdx.x;
    const int bx = blockIdx.x, kh = blockIdx.y, b = blockIdx.z;

    if (bx == 0 && kh == 0 && b == 0 && tid < 64) {
        if (tid < 36) {
            g_cnt[tid] = 0;
            g_minx[tid] = 0x7fffffff; g_maxx[tid] = -1;
            g_miny[tid] = 0x7fffffff; g_maxy[tid] = -1;
        }
        if (tid == 63) g_done = 0;
    }

    const float* in; const float* w; float* out; int P, p0;
    if (bx < TILES1) { in = f1in; w = w1; out = g_f1s[kh]; P = P1; p0 = bx * 128; }
    else             { in = f2in; w = w2; out = g_f2s[kh]; P = P2; p0 = (bx - TILES1) * 128; }
    const float* inb = in + (size_t)b * CIN * P;
    const int k0base = kh * 256;

    const int lane = tid & 31;          // pixel group: px = p0 + lane*4
    const int to8  = (tid >> 5) * 8;    // oc group (warp-uniform)

    const uint32_t as_base = (uint32_t)__cvta_generic_to_shared(&As[0][0][0]);

    float2 acc[8][2];
#pragma unroll
    for (int j = 0; j < 8; j++) { acc[j][0] = make_float2(0.f,0.f); acc[j][1] = make_float2(0.f,0.f); }

    float br[8];

    // ---- prologue ----
    {
        const int k0 = k0base;
#pragma unroll
        for (int q = 0; q < 4; q++) {
            int l = tid + q * 256;
            int row = l >> 5, c4 = l & 31;
            int px = p0 + c4 * 4; if (px > P - 4) px = P - 4;
            cp16(as_base + (uint32_t)(row * 128 + c4 * 4) * 4,
                 inb + (size_t)(k0 + row) * P + px);
        }
        cp_commit();
#pragma unroll
        for (int q = 0; q < 8; q++) {
            int l = tid + q * 256;
            int o = l >> 5, kk = l & 31;
            br[q] = w[o * CIN + k0 + kk];
        }
#pragma unroll
        for (int q = 0; q < 8; q++) {
            int l = tid + q * 256;
            int o = l >> 5, kk = l & 31;
            Bs[0][kk][o] = make_float2(br[q], br[q]);
        }
        cp_wait0();
        __syncthreads();
    }

#pragma unroll 1
    for (int kb = 0; kb < 8; kb++) {
        const int cb = kb & 1;
        const int nb = cb ^ 1;
        if (kb < 7) {
            const int k0 = k0base + (kb + 1) * 32;
#pragma unroll
            for (int q = 0; q < 4; q++) {
                int l = tid + q * 256;
                int row = l >> 5, c4 = l & 31;
                int px = p0 + c4 * 4; if (px > P - 4) px = P - 4;
                cp16(as_base + (uint32_t)(nb * 32 * 128 + row * 128 + c4 * 4) * 4,
                     inb + (size_t)(k0 + row) * P + px);
            }
            cp_commit();
#pragma unroll
            for (int q = 0; q < 8; q++) {
                int l = tid + q * 256;
                int o = l >> 5, kk = l & 31;
                br[q] = w[o * CIN + k0 + kk];
            }
        }
        // ---- compute ----
#pragma unroll
        for (int kk = 0; kk < 32; kk++) {
            float4 av = *(const float4*)&As[cb][kk][lane * 4];
            float4 b0 = *(const float4*)&Bs[cb][kk][to8];
            float4 b1 = *(const float4*)&Bs[cb][kk][to8 + 2];
            float4 b2 = *(const float4*)&Bs[cb][kk][to8 + 4];
            float4 b3 = *(const float4*)&Bs[cb][kk][to8 + 6];
            float2 ap0 = make_float2(av.x, av.y);
            float2 ap1 = make_float2(av.z, av.w);
            float2 bv[8] = { {b0.x,b0.y},{b0.z,b0.w},{b1.x,b1.y},{b1.z,b1.w},
                             {b2.x,b2.y},{b2.z,b2.w},{b3.x,b3.y},{b3.z,b3.w} };
#pragma unroll
            for (int j = 0; j < 8; j++) {
                acc[j][0] = ffma2(ap0, bv[j], acc[j][0]);
                acc[j][1] = ffma2(ap1, bv[j], acc[j][1]);
            }
        }
        __syncthreads();
        if (kb < 7) {
#pragma unroll
            for (int q = 0; q < 8; q++) {
                int l = tid + q * 256;
                int o = l >> 5, kk = l & 31;
                Bs[nb][kk][o] = make_float2(br[q], br[q]);
            }
            cp_wait0();
            __syncthreads();
        }
    }

    // ---- store partial sums (bias/relu deferred to fuse) ----
    float* outb = out + (size_t)b * HID * P;
    const int px0 = p0 + lane * 4;
    if (px0 < P) {
#pragma unroll
        for (int j = 0; j < 8; j++) {
            int oc = to8 + j;
            float4 v = make_float4(acc[j][0].x, acc[j][0].y, acc[j][1].x, acc[j][1].y);
            *(float4*)&outb[(size_t)oc * P + px0] = v;
        }
    }
}

// ============================================================
// Stage 2: logits_small = wc * (relu(f1)+up2(relu(f2))) + bc at 60x80.
// ============================================================
__global__ void __launch_bounds__(256)
fuse_kernel(const float* __restrict__ wc, const float* __restrict__ bc,
            const float* __restrict__ b1, const float* __restrict__ b2)
{
    __shared__ float s_wc[NCLS * HID];
    __shared__ float s_b1[HID], s_b2[HID], s_bc[NCLS];
    const int tid = threadIdx.x;
    for (int i = tid; i < NCLS * HID; i += 256) s_wc[i] = wc[i];
    if (tid < HID) { s_b1[tid] = b1[tid]; s_b2[tid] = b2[tid]; }
    if (tid < NCLS) s_bc[tid] = bc[tid];
    __syncthreads();

    const int pl = tid >> 1;
    const int hh = (tid & 1) * 32;
    const int p = blockIdx.x * 128 + pl;
    const int b = blockIdx.y;
    const bool valid = (p < P1);
    const int pp = valid ? p : P1 - 1;
    const int y = pp / W1, x = pp % W1;

    float fx = 0.5f * x - 0.25f;
    int ix0 = (int)floorf(fx); float tx = fx - (float)ix0;
    int ix0c = max(ix0, 0), ix1c = min(ix0 + 1, W2 - 1);
    float fy = 0.5f * y - 0.25f;
    int iy0 = (int)floorf(fy); float ty = fy - (float)iy0;
    int iy0c = max(iy0, 0), iy1c = min(iy0 + 1, H2 - 1);
    int i00 = iy0c * W2 + ix0c, i01 = iy0c * W2 + ix1c;
    int i10 = iy1c * W2 + ix0c, i11 = iy1c * W2 + ix1c;

    const float* f1a = g_f1s[0] + (size_t)b * HID * P1 + pp;
    const float* f1b = g_f1s[1] + (size_t)b * HID * P1 + pp;
    const float* f2a = g_f2s[0] + (size_t)b * HID * P2;
    const float* f2b = g_f2s[1] + (size_t)b * HID * P2;

    float acc[NCLS];
#pragma unroll
    for (int c = 0; c < NCLS; c++) acc[c] = 0.f;

#pragma unroll 4
    for (int h = hh; h < hh + 32; h++) {
        float s = fmaxf(f1a[(size_t)h * P1] + f1b[(size_t)h * P1] + s_b1[h], 0.f);
        const float* ca = f2a + (size_t)h * P2;
        const float* cb2 = f2b + (size_t)h * P2;
        float bb = s_b2[h];
        float v00 = fmaxf(ca[i00] + cb2[i00] + bb, 0.f);
        float v01 = fmaxf(ca[i01] + cb2[i01] + bb, 0.f);
        float v10 = fmaxf(ca[i10] + cb2[i10] + bb, 0.f);
        float v11 = fmaxf(ca[i11] + cb2[i11] + bb, 0.f);
        float v0 = v00 + tx * (v01 - v00);
        float v1 = v10 + tx * (v11 - v10);
        s += v0 + ty * (v1 - v0);
#pragma unroll
        for (int c = 0; c < NCLS; c++) acc[c] = fmaf(s_wc[c * HID + h], s, acc[c]);
    }

#pragma unroll
    for (int c = 0; c < NCLS; c++)
        acc[c] += __shfl_xor_sync(0xffffffffu, acc[c], 1);

    if ((tid & 1) == 0 && valid) {
        float* lsb = g_ls + (size_t)b * NCLS * P1 + p;
#pragma unroll
        for (int c = 0; c < NCLS; c++) lsb[(size_t)c * P1] = acc[c] + s_bc[c];
    }
}

// ============================================================
// Stage 3: resize8 -> softmax -> prob + seg + bbox; last block finalizes.
// ============================================================
__global__ void __launch_bounds__(256)
resize_kernel(float* __restrict__ out)
{
    __shared__ float st[NCLS][3][18];
    __shared__ int s_cnt[9], s_minx[9], s_maxx[9], s_miny[9], s_maxy[9];
    __shared__ unsigned s_ticket;

    const int tx0 = threadIdx.x, ty0 = threadIdx.y;
    const int tid = ty0 * 32 + tx0;
    if (tid < 9) {
        s_cnt[tid] = 0;
        s_minx[tid] = 0x7fffffff; s_maxx[tid] = -1;
        s_miny[tid] = 0x7fffffff; s_maxy[tid] = -1;
    }

    const int bx = blockIdx.x, by = blockIdx.y, b = blockIdx.z;
    const float* ls = g_ls + (size_t)b * NCLS * P1;

    for (int i = tid; i < NCLS * 3 * 18; i += 256) {
        int c = i / 54; int rk = i % 54; int r = rk / 18; int k = rk % 18;
        int col = min(max(bx * 16 - 1 + k, 0), W1 - 1);
        int row = min(max(by - 1 + r, 0), H1 - 1);
        st[c][r][k] = ls[(size_t)c * P1 + row * W1 + col];
    }
    __syncthreads();

    const int Xb = bx * 128 + tx0 * 4;
    const int Y  = by * 8 + ty0;
    const int odd = tx0 & 1;
    const int c0 = (tx0 >> 1) + odd;
    const int r0 = (ty0 < 4) ? 0 : 1;
    const float ty = (ty0 < 4) ? (float)(2 * ty0 + 9) * (1.f / 16.f)
                               : (float)(2 * ty0 - 7) * (1.f / 16.f);
    float txw[4];
#pragma unroll
    for (int j = 0; j < 4; j++) {
        int jx = odd * 4 + j;
        txw[j] = (jx < 4) ? (float)(2 * jx + 9) * (1.f / 16.f)
                          : (float)(2 * jx - 7) * (1.f / 16.f);
    }

    float Av[NCLS], Dv[NCLS];
#pragma unroll
    for (int c = 0; c < NCLS; c++) {
        float a0 = st[c][r0][c0],     b0v = st[c][r0][c0 + 1];
        float a1 = st[c][r0 + 1][c0], b1v = st[c][r0 + 1][c0 + 1];
        float A = a0 + ty * (a1 - a0);
        float B = b0v + ty * (b1v - b0v);
        Av[c] = A; Dv[c] = B - A;
    }

    float e[4][NCLS];
    int arg[4];
    float inv[4];
#pragma unroll
    for (int j = 0; j < 4; j++) {
        float mm = -1e30f; int aa = 0;
#pragma unroll
        for (int c = 0; c < NCLS; c++) {
            float v = fmaf(txw[j], Dv[c], Av[c]);
            e[j][c] = v;
            if (v > mm) { mm = v; aa = c; }
        }
        arg[j] = aa;
        float s = 0.f;
#pragma unroll
        for (int c = 0; c < NCLS; c++) {
            float ex = __expf(e[j][c] - mm);
            e[j][c] = ex; s += ex;
        }
        inv[j] = 1.f / s;
    }

    const size_t base = (size_t)b * NCLS * PO + (size_t)Y * WO + Xb;
#pragma unroll
    for (int c = 0; c < NCLS; c++) {
        float4 v4 = make_float4(e[0][c] * inv[0], e[1][c] * inv[1],
                                e[2][c] * inv[2], e[3][c] * inv[3]);
        *(float4*)&out[base + (size_t)c * PO] = v4;
    }
    *(float4*)&out[PROB_ELEMS + (size_t)b * PO + (size_t)Y * WO + Xb] =
        make_float4((float)arg[0], (float)arg[1], (float)arg[2], (float)arg[3]);

#pragma unroll
    for (int j = 0; j < 4; j++) {
        int c = arg[j];
        if (c < 1 || c > 9) continue;
        bool dup = false;
#pragma unroll
        for (int jj = 0; jj < 4; jj++) if (jj < j && arg[jj] == c) dup = true;
        if (dup) continue;
        int cnt = 1, mx = Xb + j;
#pragma unroll
        for (int jj = 0; jj < 4; jj++) if (jj > j && arg[jj] == c) { cnt++; mx = Xb + jj; }
        int k = c - 1;
        atomicAdd(&s_cnt[k], cnt);
        atomicMin(&s_minx[k], Xb + j); atomicMax(&s_maxx[k], mx);
        atomicMin(&s_miny[k], Y);      atomicMax(&s_maxy[k], Y);
    }
    __syncthreads();
    if (tid < 9 && s_cnt[tid] > 0) {
        int g = b * 9 + tid;
        atomicAdd(&g_cnt[g], s_cnt[tid]);
        atomicMin(&g_minx[g], s_minx[tid]); atomicMax(&g_maxx[g], s_maxx[tid]);
        atomicMin(&g_miny[g], s_miny[tid]); atomicMax(&g_maxy[g], s_maxy[tid]);
    }

    __threadfence();
    __syncthreads();
    if (tid == 0) s_ticket = atomicAdd(&g_done, 1u);
    __syncthreads();
    if (s_ticket == RS_BLOCKS - 1 && tid < 36) {
        __threadfence();
        int cnt = atomicAdd(&g_cnt[tid], 0);
        float* row = out + PROB_ELEMS + SEG_ELEMS + (size_t)tid * 6;
        if (cnt >= THRESH) {
            row[0] = (float)(tid / 9);
            row[1] = (float)atomicAdd(&g_minx[tid], 0);
            row[2] = (float)atomicAdd(&g_miny[tid], 0);
            row[3] = (float)atomicAdd(&g_maxx[tid], 0);
            row[4] = (float)atomicAdd(&g_maxy[tid], 0);
            row[5] = (float)(tid % 9 + 1);
        } else {
            row[0] = -1.f; row[1] = -1.f; row[2] = -1.f;
            row[3] = -1.f; row[4] = -1.f; row[5] = -1.f;
        }
    }
}

// ============================================================
extern "C" void kernel_launch(void* const* d_in, const int* in_sizes, int n_in,
                              void* d_out, int out_size)
{
    const float* feature1 = (const float*)d_in[0];
    const float* feature2 = (const float*)d_in[1];
    const float* w1 = (const float*)d_in[2];
    const float* b1 = (const float*)d_in[3];
    const float* w2 = (const float*)d_in[4];
    const float* b2 = (const float*)d_in[5];
    const float* wc = (const float*)d_in[6];
    const float* bc = (const float*)d_in[7];
    float* out = (float*)d_out;

    conv_kernel<<<dim3(TILES1 + TILES2, 2, BATCH), 256>>>(feature1, feature2, w1, w2);
    fuse_kernel<<<dim3(38, BATCH), 256>>>(wc, bc, b1, b2);
    resize_kernel<<<dim3(RS_BX, RS_BY, BATCH), dim3(32, 8)>>>(out);
}

// round 7
// speedup vs baseline: 1.5151x; 1.0208x over previous
#include <cuda_runtime.h>
#include <math.h>
#include <stdint.h>

#define BATCH 4
#define CIN   512
#define HID   64
#define NCLS  11
#define H1    60
#define W1    80
#define P1    4800
#define H2    30
#define W2    40
#define P2    1200
#define HO    480
#define WO    640
#define PO    307200
#define THRESH 500

#define PROB_ELEMS ((size_t)BATCH*NCLS*PO)
#define SEG_ELEMS  ((size_t)BATCH*PO)

#define TILES1 38            // ceil(4800/128)
#define TILES2 10            // ceil(1200/128)
#define RS_BX  5
#define RS_BY  60
#define RS_BLOCKS (RS_BX*RS_BY*BATCH)   // 1200

// -------- scratch --------
__device__ float g_f1s[2][BATCH*HID*P1];
__device__ float g_f2s[2][BATCH*HID*P2];
__device__ float g_ls[BATCH*NCLS*P1];
__device__ int g_cnt[36], g_minx[36], g_maxx[36], g_miny[36], g_maxy[36];
__device__ unsigned g_done;

__device__ __forceinline__ float2 ffma2(float2 a, float2 b, float2 c) {
    float2 d;
    asm("fma.rn.f32x2 %0, %1, %2, %3;"
        : "=l"(*(unsigned long long*)&d)
        : "l"(*(unsigned long long*)&a),
          "l"(*(unsigned long long*)&b),
          "l"(*(unsigned long long*)&c));
    return d;
}

__device__ __forceinline__ void cp16(uint32_t s, const float* g) {
    asm volatile("cp.async.cg.shared.global [%0], [%1], 16;" :: "r"(s), "l"(g));
}
__device__ __forceinline__ void cp_commit() {
    asm volatile("cp.async.commit_group;");
}
__device__ __forceinline__ void cp_wait0() {
    asm volatile("cp.async.wait_group 0;");
}

// ============================================================
// Stage 1: 1x1 conv GEMM, K-split 2, cp.async double-buffered.
// Tile: 128 px x 64 oc x 256 ch. 128 threads.
// Thread: 8 px x 8 oc = 32 ffma2/kk, 6 LDS/kk (A dedup + B broadcast).
// ============================================================
__global__ void __launch_bounds__(128)
conv_kernel(const float* __restrict__ f1in, const float* __restrict__ f2in,
            const float* __restrict__ w1, const float* __restrict__ w2)
{
    __shared__ alignas(16) float  As[2][32][128];   // 32 KB
    __shared__ alignas(16) float2 Bs[2][32][66];    // 33.8 KB (oc duplicated (w,w))

    const int tid = threadIdx.x;
    const int bx = blockIdx.x, kh = blockIdx.y, b = blockIdx.z;

    if (bx == 0 && kh == 0 && b == 0 && tid < 64) {
        if (tid < 36) {
            g_cnt[tid] = 0;
            g_minx[tid] = 0x7fffffff; g_maxx[tid] = -1;
            g_miny[tid] = 0x7fffffff; g_maxy[tid] = -1;
        }
        if (tid == 63) g_done = 0;
    }

    const float* in; const float* w; float* out; int P, p0;
    if (bx < TILES1) { in = f1in; w = w1; out = g_f1s[kh]; P = P1; p0 = bx * 128; }
    else             { in = f2in; w = w2; out = g_f2s[kh]; P = P2; p0 = (bx - TILES1) * 128; }
    const float* inb = in + (size_t)b * CIN * P;
    const int k0base = kh * 256;

    const int pg  = tid & 15;           // pixel group: px = p0 + pg*8
    const int og8 = (tid >> 4) * 8;     // oc group (half-warp uniform)

    const uint32_t as_base = (uint32_t)__cvta_generic_to_shared(&As[0][0][0]);

    float2 acc[8][4];                    // [oc][px-pair]
#pragma unroll
    for (int j = 0; j < 8; j++)
#pragma unroll
        for (int i = 0; i < 4; i++) acc[j][i] = make_float2(0.f, 0.f);

    float br[16];

    // ---- prologue: k-block 0 ----
    {
        const int k0 = k0base;
#pragma unroll
        for (int q = 0; q < 8; q++) {
            int l = tid + q * 128;
            int row = l >> 5, c4 = l & 31;
            int px = p0 + c4 * 4; if (px > P - 4) px = P - 4;
            cp16(as_base + (uint32_t)(row * 128 + c4 * 4) * 4,
                 inb + (size_t)(k0 + row) * P + px);
        }
        cp_commit();
#pragma unroll
        for (int q = 0; q < 16; q++) {
            int l = tid + q * 128;
            int o = l >> 5, kk = l & 31;
            br[q] = w[o * CIN + k0 + kk];
        }
#pragma unroll
        for (int q = 0; q < 16; q++) {
            int l = tid + q * 128;
            int o = l >> 5, kk = l & 31;
            Bs[0][kk][o] = make_float2(br[q], br[q]);
        }
        cp_wait0();
        __syncthreads();
    }

#pragma unroll 1
    for (int kb = 0; kb < 8; kb++) {
        const int cb = kb & 1;
        const int nb = cb ^ 1;
        if (kb < 7) {
            const int k0 = k0base + (kb + 1) * 32;
#pragma unroll
            for (int q = 0; q < 8; q++) {
                int l = tid + q * 128;
                int row = l >> 5, c4 = l & 31;
                int px = p0 + c4 * 4; if (px > P - 4) px = P - 4;
                cp16(as_base + (uint32_t)(nb * 32 * 128 + row * 128 + c4 * 4) * 4,
                     inb + (size_t)(k0 + row) * P + px);
            }
            cp_commit();
#pragma unroll
            for (int q = 0; q < 16; q++) {
                int l = tid + q * 128;
                int o = l >> 5, kk = l & 31;
                br[q] = w[o * CIN + k0 + kk];      // LDG latency overlapped w/ compute
            }
        }
        // ---- compute on buffer cb ----
#pragma unroll
        for (int kk = 0; kk < 32; kk++) {
            float4 av0 = *(const float4*)&As[cb][kk][pg * 8];
            float4 av1 = *(const float4*)&As[cb][kk][pg * 8 + 4];
            float4 b0 = *(const float4*)&Bs[cb][kk][og8];
            float4 b1 = *(const float4*)&Bs[cb][kk][og8 + 2];
            float4 b2 = *(const float4*)&Bs[cb][kk][og8 + 4];
            float4 b3 = *(const float4*)&Bs[cb][kk][og8 + 6];
            float2 ap[4] = { {av0.x,av0.y},{av0.z,av0.w},{av1.x,av1.y},{av1.z,av1.w} };
            float2 bv[8] = { {b0.x,b0.y},{b0.z,b0.w},{b1.x,b1.y},{b1.z,b1.w},
                             {b2.x,b2.y},{b2.z,b2.w},{b3.x,b3.y},{b3.z,b3.w} };
#pragma unroll
            for (int j = 0; j < 8; j++)
#pragma unroll
                for (int i = 0; i < 4; i++)
                    acc[j][i] = ffma2(ap[i], bv[j], acc[j][i]);
        }
        // writes below target buffers whose readers all finished at the sync
        // that ended iteration kb-1 -> single barrier per iteration.
        if (kb < 7) {
#pragma unroll
            for (int q = 0; q < 16; q++) {
                int l = tid + q * 128;
                int o = l >> 5, kk = l & 31;
                Bs[nb][kk][o] = make_float2(br[q], br[q]);
            }
            cp_wait0();
            __syncthreads();
        }
    }

    // ---- store partial sums (bias/relu deferred to fuse) ----
    float* outb = out + (size_t)b * HID * P;
    const int px0 = p0 + pg * 8;
    if (px0 < P) {                       // P % 8 == 0 -> full 8-px strip valid
#pragma unroll
        for (int j = 0; j < 8; j++) {
            int oc = og8 + j;
            float* op = outb + (size_t)oc * P;
            *(float4*)&op[px0]     = make_float4(acc[j][0].x, acc[j][0].y, acc[j][1].x, acc[j][1].y);
            *(float4*)&op[px0 + 4] = make_float4(acc[j][2].x, acc[j][2].y, acc[j][3].x, acc[j][3].y);
        }
    }
}

// ============================================================
// Stage 2: logits_small = wc * (relu(f1)+up2(relu(f2))) + bc at 60x80.
// ============================================================
__global__ void __launch_bounds__(256)
fuse_kernel(const float* __restrict__ wc, const float* __restrict__ bc,
            const float* __restrict__ b1, const float* __restrict__ b2)
{
    __shared__ float s_wc[NCLS * HID];
    __shared__ float s_b1[HID], s_b2[HID], s_bc[NCLS];
    const int tid = threadIdx.x;
    for (int i = tid; i < NCLS * HID; i += 256) s_wc[i] = wc[i];
    if (tid < HID) { s_b1[tid] = b1[tid]; s_b2[tid] = b2[tid]; }
    if (tid < NCLS) s_bc[tid] = bc[tid];
    __syncthreads();

    const int pl = tid >> 1;
    const int hh = (tid & 1) * 32;
    const int p = blockIdx.x * 128 + pl;
    const int b = blockIdx.y;
    const bool valid = (p < P1);
    const int pp = valid ? p : P1 - 1;
    const int y = pp / W1, x = pp % W1;

    float fx = 0.5f * x - 0.25f;
    int ix0 = (int)floorf(fx); float tx = fx - (float)ix0;
    int ix0c = max(ix0, 0), ix1c = min(ix0 + 1, W2 - 1);
    float fy = 0.5f * y - 0.25f;
    int iy0 = (int)floorf(fy); float ty = fy - (float)iy0;
    int iy0c = max(iy0, 0), iy1c = min(iy0 + 1, H2 - 1);
    int i00 = iy0c * W2 + ix0c, i01 = iy0c * W2 + ix1c;
    int i10 = iy1c * W2 + ix0c, i11 = iy1c * W2 + ix1c;

    const float* f1a = g_f1s[0] + (size_t)b * HID * P1 + pp;
    const float* f1b = g_f1s[1] + (size_t)b * HID * P1 + pp;
    const float* f2a = g_f2s[0] + (size_t)b * HID * P2;
    const float* f2b = g_f2s[1] + (size_t)b * HID * P2;

    float acc[NCLS];
#pragma unroll
    for (int c = 0; c < NCLS; c++) acc[c] = 0.f;

#pragma unroll 4
    for (int h = hh; h < hh + 32; h++) {
        float s = fmaxf(f1a[(size_t)h * P1] + f1b[(size_t)h * P1] + s_b1[h], 0.f);
        const float* ca = f2a + (size_t)h * P2;
        const float* cb2 = f2b + (size_t)h * P2;
        float bb = s_b2[h];
        float v00 = fmaxf(ca[i00] + cb2[i00] + bb, 0.f);
        float v01 = fmaxf(ca[i01] + cb2[i01] + bb, 0.f);
        float v10 = fmaxf(ca[i10] + cb2[i10] + bb, 0.f);
        float v11 = fmaxf(ca[i11] + cb2[i11] + bb, 0.f);
        float v0 = v00 + tx * (v01 - v00);
        float v1 = v10 + tx * (v11 - v10);
        s += v0 + ty * (v1 - v0);
#pragma unroll
        for (int c = 0; c < NCLS; c++) acc[c] = fmaf(s_wc[c * HID + h], s, acc[c]);
    }

#pragma unroll
    for (int c = 0; c < NCLS; c++)
        acc[c] += __shfl_xor_sync(0xffffffffu, acc[c], 1);

    if ((tid & 1) == 0 && valid) {
        float* lsb = g_ls + (size_t)b * NCLS * P1 + p;
#pragma unroll
        for (int c = 0; c < NCLS; c++) lsb[(size_t)c * P1] = acc[c] + s_bc[c];
    }
}

// ============================================================
// Stage 3: resize8 -> softmax -> prob + seg + bbox; last block finalizes.
// ============================================================
__global__ void __launch_bounds__(256)
resize_kernel(float* __restrict__ out)
{
    __shared__ float st[NCLS][3][18];
    __shared__ int s_cnt[9], s_minx[9], s_maxx[9], s_miny[9], s_maxy[9];
    __shared__ unsigned s_ticket;

    const int tx0 = threadIdx.x, ty0 = threadIdx.y;
    const int tid = ty0 * 32 + tx0;
    if (tid < 9) {
        s_cnt[tid] = 0;
        s_minx[tid] = 0x7fffffff; s_maxx[tid] = -1;
        s_miny[tid] = 0x7fffffff; s_maxy[tid] = -1;
    }

    const int bx = blockIdx.x, by = blockIdx.y, b = blockIdx.z;
    const float* ls = g_ls + (size_t)b * NCLS * P1;

    for (int i = tid; i < NCLS * 3 * 18; i += 256) {
        int c = i / 54; int rk = i % 54; int r = rk / 18; int k = rk % 18;
        int col = min(max(bx * 16 - 1 + k, 0), W1 - 1);
        int row = min(max(by - 1 + r, 0), H1 - 1);
        st[c][r][k] = ls[(size_t)c * P1 + row * W1 + col];
    }
    __syncthreads();

    const int Xb = bx * 128 + tx0 * 4;
    const int Y  = by * 8 + ty0;
    const int odd = tx0 & 1;
    const int c0 = (tx0 >> 1) + odd;
    const int r0 = (ty0 < 4) ? 0 : 1;
    const float ty = (ty0 < 4) ? (float)(2 * ty0 + 9) * (1.f / 16.f)
                               : (float)(2 * ty0 - 7) * (1.f / 16.f);
    float txw[4];
#pragma unroll
    for (int j = 0; j < 4; j++) {
        int jx = odd * 4 + j;
        txw[j] = (jx < 4) ? (float)(2 * jx + 9) * (1.f / 16.f)
                          : (float)(2 * jx - 7) * (1.f / 16.f);
    }

    float Av[NCLS], Dv[NCLS];
#pragma unroll
    for (int c = 0; c < NCLS; c++) {
        float a0 = st[c][r0][c0],     b0v = st[c][r0][c0 + 1];
        float a1 = st[c][r0 + 1][c0], b1v = st[c][r0 + 1][c0 + 1];
        float A = a0 + ty * (a1 - a0);
        float B = b0v + ty * (b1v - b0v);
        Av[c] = A; Dv[c] = B - A;
    }

    float e[4][NCLS];
    int arg[4];
    float inv[4];
#pragma unroll
    for (int j = 0; j < 4; j++) {
        float mm = -1e30f; int aa = 0;
#pragma unroll
        for (int c = 0; c < NCLS; c++) {
            float v = fmaf(txw[j], Dv[c], Av[c]);
            e[j][c] = v;
            if (v > mm) { mm = v; aa = c; }
        }
        arg[j] = aa;
        float s = 0.f;
#pragma unroll
        for (int c = 0; c < NCLS; c++) {
            float ex = __expf(e[j][c] - mm);
            e[j][c] = ex; s += ex;
        }
        inv[j] = 1.f / s;
    }

    const size_t base = (size_t)b * NCLS * PO + (size_t)Y * WO + Xb;
#pragma unroll
    for (int c = 0; c < NCLS; c++) {
        float4 v4 = make_float4(e[0][c] * inv[0], e[1][c] * inv[1],
                                e[2][c] * inv[2], e[3][c] * inv[3]);
        *(float4*)&out[base + (size_t)c * PO] = v4;
    }
    *(float4*)&out[PROB_ELEMS + (size_t)b * PO + (size_t)Y * WO + Xb] =
        make_float4((float)arg[0], (float)arg[1], (float)arg[2], (float)arg[3]);

#pragma unroll
    for (int j = 0; j < 4; j++) {
        int c = arg[j];
        if (c < 1 || c > 9) continue;
        bool dup = false;
#pragma unroll
        for (int jj = 0; jj < 4; jj++) if (jj < j && arg[jj] == c) dup = true;
        if (dup) continue;
        int cnt = 1, mx = Xb + j;
#pragma unroll
        for (int jj = 0; jj < 4; jj++) if (jj > j && arg[jj] == c) { cnt++; mx = Xb + jj; }
        int k = c - 1;
        atomicAdd(&s_cnt[k], cnt);
        atomicMin(&s_minx[k], Xb + j); atomicMax(&s_maxx[k], mx);
        atomicMin(&s_miny[k], Y);      atomicMax(&s_maxy[k], Y);
    }
    __syncthreads();
    if (tid < 9 && s_cnt[tid] > 0) {
        int g = b * 9 + tid;
        atomicAdd(&g_cnt[g], s_cnt[tid]);
        atomicMin(&g_minx[g], s_minx[tid]); atomicMax(&g_maxx[g], s_maxx[tid]);
        atomicMin(&g_miny[g], s_miny[tid]); atomicMax(&g_maxy[g], s_maxy[tid]);
    }

    __threadfence();
    __syncthreads();
    if (tid == 0) s_ticket = atomicAdd(&g_done, 1u);
    __syncthreads();
    if (s_ticket == RS_BLOCKS - 1 && tid < 36) {
        __threadfence();
        int cnt = atomicAdd(&g_cnt[tid], 0);
        float* row = out + PROB_ELEMS + SEG_ELEMS + (size_t)tid * 6;
        if (cnt >= THRESH) {
            row[0] = (float)(tid / 9);
            row[1] = (float)atomicAdd(&g_minx[tid], 0);
            row[2] = (float)atomicAdd(&g_miny[tid], 0);
            row[3] = (float)atomicAdd(&g_maxx[tid], 0);
            row[4] = (float)atomicAdd(&g_maxy[tid], 0);
            row[5] = (float)(tid % 9 + 1);
        } else {
            row[0] = -1.f; row[1] = -1.f; row[2] = -1.f;
            row[3] = -1.f; row[4] = -1.f; row[5] = -1.f;
        }
    }
}

// ============================================================
extern "C" void kernel_launch(void* const* d_in, const int* in_sizes, int n_in,
                              void* d_out, int out_size)
{
    const float* feature1 = (const float*)d_in[0];
    const float* feature2 = (const float*)d_in[1];
    const float* w1 = (const float*)d_in[2];
    const float* b1 = (const float*)d_in[3];
    const float* w2 = (const float*)d_in[4];
    const float* b2 = (const float*)d_in[5];
    const float* wc = (const float*)d_in[6];
    const float* bc = (const float*)d_in[7];
    float* out = (float*)d_out;

    conv_kernel<<<dim3(TILES1 + TILES2, 2, BATCH), 128>>>(feature1, feature2, w1, w2);
    fuse_kernel<<<dim3(38, BATCH), 256>>>(wc, bc, b1, b2);
    resize_kernel<<<dim3(RS_BX, RS_BY, BATCH), dim3(32, 8)>>>(out);
}